// round 3
// baseline (speedup 1.0000x reference)
#include <cuda_runtime.h>
#include <cstdint>

// LinearKoopmanLayer: per-(b,f) complex rotation of channel pair (2f, 2f+1).
// x: (B=256, 2F=128, T=1024) fp32. out same shape.
//   c = amp[f]^dt[b] * cos(freq[f]*dt[b])
//   s = amp[f]^dt[b] * sin(freq[f]*dt[b])
//   out[b,2f,t]   = c*x[b,2f,t] - s*x[b,2f+1,t]
//   out[b,2f+1,t] = s*x[b,2f,t] + c*x[b,2f+1,t]

#define B_DIM 256
#define F_DIM 64
#define T_DIM 1024
#define T_VEC (T_DIM / 4)   // 256 float4 per row

__global__ __launch_bounds__(256, 8)
void koopman_kernel(const float* __restrict__ x,
                    const float* __restrict__ delta_t,
                    const float* __restrict__ amplitudes,
                    const float* __restrict__ frequencies,
                    float* __restrict__ out) {
    const int bf = blockIdx.x;          // b*F + f
    const int b  = bf >> 6;             // F = 64
    const int f  = bf & 63;

    const float d   = __ldg(&delta_t[b]);
    const float amp = __ldg(&amplitudes[f]);
    const float frq = __ldg(&frequencies[f]);

    const float a   = powf(amp, d);     // amp in [0.7,1.3], d in [0.5,2] — well-conditioned
    const float ang = frq * d;
    float s, c;
    sincosf(ang, &s, &c);
    c *= a;
    s *= a;

    // channel row for x0 is 2f within batch b: global row = b*128 + 2f = 2*bf
    const size_t base = (size_t)bf * (2 * T_DIM);   // float offset of x0 row
    const float4* __restrict__ x0 = reinterpret_cast<const float4*>(x + base);
    const float4* __restrict__ x1 = x0 + T_VEC;     // next row, 1024 floats later
    float4* __restrict__ o0 = reinterpret_cast<float4*>(out + base);
    float4* __restrict__ o1 = o0 + T_VEC;

    const int t = threadIdx.x;          // 0..255, one float4 each
    const float4 v0 = x0[t];
    const float4 v1 = x1[t];

    float4 r0, r1;
    r0.x = c * v0.x - s * v1.x;  r1.x = s * v0.x + c * v1.x;
    r0.y = c * v0.y - s * v1.y;  r1.y = s * v0.y + c * v1.y;
    r0.z = c * v0.z - s * v1.z;  r1.z = s * v0.z + c * v1.z;
    r0.w = c * v0.w - s * v1.w;  r1.w = s * v0.w + c * v1.w;

    o0[t] = r0;
    o1[t] = r1;
}

extern "C" void kernel_launch(void* const* d_in, const int* in_sizes, int n_in,
                              void* d_out, int out_size) {
    const float* x           = (const float*)d_in[0];
    const float* delta_t     = (const float*)d_in[1];
    const float* amplitudes  = (const float*)d_in[2];
    const float* frequencies = (const float*)d_in[3];
    float* out = (float*)d_out;

    dim3 grid(B_DIM * F_DIM);   // 16384 blocks, one per (b,f)
    dim3 block(256);
    koopman_kernel<<<grid, block>>>(x, delta_t, amplitudes, frequencies, out);
}